// round 1
// baseline (speedup 1.0000x reference)
#include <cuda_runtime.h>
#include <math.h>

#define N_ROWS 4096
#define D      256
#define TWO_N  8192
#define BM 128
#define BN 128
#define BK 16
#define NCOLTILES (TWO_N / BN)   // 64
#define NROWTILES (N_ROWS / BM)  // 32

__device__ __constant__ float c_invT = 14.285714285714286f; // 1/0.07

// Scratch (device globals; no allocation anywhere)
__device__ float g_Zn[TWO_N * D];               // normalized [z1n; z2n]
__device__ float g_partial[N_ROWS * NCOLTILES]; // [row][colTile] exp-row-sums
__device__ float g_loss[N_ROWS];

// ---------------------------------------------------------------------------
// Kernel 1: L2-normalize rows of z1 and z2 into g_Zn. One warp per row.
// ---------------------------------------------------------------------------
__global__ void __launch_bounds__(256) normalize_kernel(const float* __restrict__ z1,
                                                        const float* __restrict__ z2) {
    const int row  = blockIdx.x * 8 + (threadIdx.x >> 5);
    const int lane = threadIdx.x & 31;
    const float* src = (row < N_ROWS) ? (z1 + (size_t)row * D)
                                      : (z2 + (size_t)(row - N_ROWS) * D);
    // 256 floats per row = 64 float4; lane handles float4 #lane and #lane+32
    float4 a = reinterpret_cast<const float4*>(src)[lane];
    float4 b = reinterpret_cast<const float4*>(src)[lane + 32];
    float ss = a.x*a.x + a.y*a.y + a.z*a.z + a.w*a.w
             + b.x*b.x + b.y*b.y + b.z*b.z + b.w*b.w;
    #pragma unroll
    for (int off = 16; off > 0; off >>= 1)
        ss += __shfl_xor_sync(0xffffffffu, ss, off);
    float norm  = sqrtf(ss);
    float scale = 1.0f / fmaxf(norm, 1e-12f);
    float* dst = g_Zn + (size_t)row * D;
    float4 oa = make_float4(a.x*scale, a.y*scale, a.z*scale, a.w*scale);
    float4 ob = make_float4(b.x*scale, b.y*scale, b.z*scale, b.w*scale);
    reinterpret_cast<float4*>(dst)[lane]      = oa;
    reinterpret_cast<float4*>(dst)[lane + 32] = ob;
}

// ---------------------------------------------------------------------------
// Kernel 2: fused sim-GEMM + exp + row-sum.
// Block (bx, by) computes sim tile rows [bx*128, +128) x cols [by*128, +128),
// exp(sim/T), reduces along the 128 columns, writes one partial per row.
// 256 threads, 8x8 register tile, BK=16 double-buffered smem.
// ---------------------------------------------------------------------------
__global__ void __launch_bounds__(256) simsum_kernel() {
    __shared__ float As[2][BK][BM];
    __shared__ float Bs[2][BK][BN];

    const int rowBase = blockIdx.x * BM;   // [0, 4096)
    const int colBase = blockIdx.y * BN;   // [0, 8192)
    const int tid = threadIdx.x;
    const int tx = tid & 15;               // 0..15 -> 8 cols each
    const int ty = tid >> 4;               // 0..15 -> 8 rows each
    const int lr = tid >> 2;               // 0..63 (load row)
    const int lc = (tid & 3) << 2;         // 0,4,8,12 (load col within k-tile)

    const float* Ag = g_Zn + (size_t)rowBase * D;
    const float* Bg = g_Zn + (size_t)colBase * D;

    float acc[8][8];
    #pragma unroll
    for (int i = 0; i < 8; i++)
        #pragma unroll
        for (int j = 0; j < 8; j++) acc[i][j] = 0.0f;

    // tile loader: 128 rows x 16 cols of A and B, stored k-major (transposed)
    auto loadTile = [&](int kk, int buf) {
        #pragma unroll
        for (int h = 0; h < 2; h++) {
            int r = lr + h * 64;
            float4 va = *reinterpret_cast<const float4*>(Ag + (size_t)r * D + kk + lc);
            As[buf][lc + 0][r] = va.x;
            As[buf][lc + 1][r] = va.y;
            As[buf][lc + 2][r] = va.z;
            As[buf][lc + 3][r] = va.w;
            float4 vb = *reinterpret_cast<const float4*>(Bg + (size_t)r * D + kk + lc);
            Bs[buf][lc + 0][r] = vb.x;
            Bs[buf][lc + 1][r] = vb.y;
            Bs[buf][lc + 2][r] = vb.z;
            Bs[buf][lc + 3][r] = vb.w;
        }
    };

    loadTile(0, 0);
    __syncthreads();

    #pragma unroll
    for (int kt = 0; kt < D / BK; kt++) {
        const int buf = kt & 1;
        if (kt + 1 < D / BK) loadTile((kt + 1) * BK, buf ^ 1);
        #pragma unroll
        for (int k = 0; k < BK; k++) {
            float a[8], b[8];
            *reinterpret_cast<float4*>(a)     = *reinterpret_cast<const float4*>(&As[buf][k][ty * 8]);
            *reinterpret_cast<float4*>(a + 4) = *reinterpret_cast<const float4*>(&As[buf][k][ty * 8 + 4]);
            *reinterpret_cast<float4*>(b)     = *reinterpret_cast<const float4*>(&Bs[buf][k][tx * 8]);
            *reinterpret_cast<float4*>(b + 4) = *reinterpret_cast<const float4*>(&Bs[buf][k][tx * 8 + 4]);
            #pragma unroll
            for (int i = 0; i < 8; i++)
                #pragma unroll
                for (int j = 0; j < 8; j++)
                    acc[i][j] = fmaf(a[i], b[j], acc[i][j]);
        }
        __syncthreads();
    }

    // Epilogue: exp(sim/T), sum across the 128 columns of this tile
    const float invT = c_invT;
    float rs[8];
    #pragma unroll
    for (int i = 0; i < 8; i++) {
        float s = 0.0f;
        #pragma unroll
        for (int j = 0; j < 8; j++) s += __expf(acc[i][j] * invT);
        rs[i] = s;
    }
    // threads with same ty are a contiguous half-warp (tx = lane&15): xor-reduce
    #pragma unroll
    for (int i = 0; i < 8; i++) {
        #pragma unroll
        for (int off = 8; off > 0; off >>= 1)
            rs[i] += __shfl_xor_sync(0xffffffffu, rs[i], off);
    }
    if (tx == 0) {
        #pragma unroll
        for (int i = 0; i < 8; i++)
            g_partial[(size_t)(rowBase + ty * 8 + i) * NCOLTILES + blockIdx.y] = rs[i];
    }
}

// ---------------------------------------------------------------------------
// Kernel 3: per-row loss. One warp per row.
// loss_i = log(total_i - exp(dot(z1n_i, z2n_0)/T)) - dot(z1n_i, z2n_i)/T
// ---------------------------------------------------------------------------
__global__ void __launch_bounds__(256) loss_kernel() {
    const int row  = blockIdx.x * 8 + (threadIdx.x >> 5);
    const int lane = threadIdx.x & 31;

    float total = g_partial[(size_t)row * NCOLTILES + lane]
                + g_partial[(size_t)row * NCOLTILES + lane + 32];

    const float4* z1r = reinterpret_cast<const float4*>(g_Zn + (size_t)row * D);
    const float4* z2r = reinterpret_cast<const float4*>(g_Zn + (size_t)(N_ROWS + row) * D);
    const float4* z20 = reinterpret_cast<const float4*>(g_Zn + (size_t)N_ROWS * D);

    float dp = 0.0f, d0 = 0.0f;
    #pragma unroll
    for (int h = 0; h < 2; h++) {
        float4 a = z1r[lane + h * 32];
        float4 b = z2r[lane + h * 32];
        float4 c = z20[lane + h * 32];
        dp += a.x*b.x + a.y*b.y + a.z*b.z + a.w*b.w;
        d0 += a.x*c.x + a.y*c.y + a.z*c.z + a.w*c.w;
    }
    #pragma unroll
    for (int off = 16; off > 0; off >>= 1) {
        total += __shfl_xor_sync(0xffffffffu, total, off);
        dp    += __shfl_xor_sync(0xffffffffu, dp, off);
        d0    += __shfl_xor_sync(0xffffffffu, d0, off);
    }
    if (lane == 0) {
        const float invT = c_invT;
        float sum_negs = total - __expf(d0 * invT);
        g_loss[row] = logf(sum_negs) - dp * invT;
    }
}

// ---------------------------------------------------------------------------
// Kernel 4: mean over 4096 rows -> d_out[0]
// ---------------------------------------------------------------------------
__global__ void __launch_bounds__(256) reduce_kernel(float* __restrict__ out) {
    __shared__ float s[256];
    float v = 0.0f;
    for (int i = threadIdx.x; i < N_ROWS; i += 256) v += g_loss[i];
    s[threadIdx.x] = v;
    __syncthreads();
    #pragma unroll
    for (int stride = 128; stride > 0; stride >>= 1) {
        if (threadIdx.x < stride) s[threadIdx.x] += s[threadIdx.x + stride];
        __syncthreads();
    }
    if (threadIdx.x == 0) out[0] = s[0] * (1.0f / N_ROWS);
}

// ---------------------------------------------------------------------------
extern "C" void kernel_launch(void* const* d_in, const int* in_sizes, int n_in,
                              void* d_out, int out_size) {
    const float* z1 = (const float*)d_in[0];
    const float* z2 = (const float*)d_in[1];
    float* out = (float*)d_out;

    normalize_kernel<<<TWO_N / 8, 256>>>(z1, z2);
    dim3 grid(NROWTILES, NCOLTILES);
    simsum_kernel<<<grid, 256>>>();
    loss_kernel<<<N_ROWS / 8, 256>>>();
    reduce_kernel<<<1, 256>>>(out);
}

// round 4
// speedup vs baseline: 3.1216x; 3.1216x over previous
#include <cuda_runtime.h>
#include <cuda_bf16.h>
#include <math.h>
#include <stdint.h>

#define N_ROWS 4096
#define D      256
#define TWO_N  8192
#define BM 128
#define BN 128
#define BK 32
#define NKT (D / BK)              // 8 k-chunks
#define NCOLTILES 64              // one partial per (row, 128-col tile)

__device__ __constant__ float c_invT = 14.285714285714286f; // 1/0.07

// Scratch (device globals; no allocation anywhere)
__device__ float          g_Zn[TWO_N * D];       // normalized fp32 (exact dots)
__device__ __nv_bfloat16  g_hi[TWO_N * D];       // bf16 hi plane
__device__ __nv_bfloat16  g_lo[TWO_N * D];       // bf16 lo plane (residual)
__device__ float          g_partial[N_ROWS * NCOLTILES];
__device__ float          g_loss[N_ROWS];

// ---------------------------------------------------------------------------
// PTX helpers (all arch-agnostic: sm_80+ baseline instructions only)
// ---------------------------------------------------------------------------
__device__ __forceinline__ uint32_t smem_to_u32(const void* p) {
    uint32_t a;
    asm("{ .reg .u64 t; cvta.to.shared.u64 t, %1; cvt.u32.u64 %0, t; }" : "=r"(a) : "l"(p));
    return a;
}
#define CP_ASYNC16(dst, src) \
    asm volatile("cp.async.cg.shared.global [%0], [%1], 16;" :: "r"(dst), "l"(src))
#define CP_COMMIT() asm volatile("cp.async.commit_group;" ::: "memory")
#define CP_WAIT(n)  asm volatile("cp.async.wait_group %0;" :: "n"(n) : "memory")

__device__ __forceinline__ void ldsm4(uint32_t* r, uint32_t addr) {
    asm volatile("ldmatrix.sync.aligned.m8n8.x4.shared.b16 {%0,%1,%2,%3}, [%4];"
        : "=r"(r[0]), "=r"(r[1]), "=r"(r[2]), "=r"(r[3]) : "r"(addr));
}
__device__ __forceinline__ void mma16816(float* c, const uint32_t* a,
                                         uint32_t b0, uint32_t b1) {
    asm volatile("mma.sync.aligned.m16n8k16.row.col.f32.bf16.bf16.f32 "
        "{%0,%1,%2,%3}, {%4,%5,%6,%7}, {%8,%9}, {%0,%1,%2,%3};"
        : "+f"(c[0]), "+f"(c[1]), "+f"(c[2]), "+f"(c[3])
        : "r"(a[0]), "r"(a[1]), "r"(a[2]), "r"(a[3]), "r"(b0), "r"(b1));
}

// smem tile layout: 128 rows x 128 bytes (8 x 16B chunks per row).
// chunks 0-3 = hi (32 bf16), chunks 4-7 = lo. XOR swizzle: chunk ^= (row & 7).
__device__ __forceinline__ uint32_t swadr(uint32_t base, int rowByte, int rm, int ch) {
    return base + rowByte + ((ch ^ rm) << 4);
}

#define OFF_B       16384
#define STAGE_BYTES 32768
#define SMEM_TOTAL  (2 * STAGE_BYTES)   // 64 KB

// ---------------------------------------------------------------------------
// Kernel 1: L2-normalize rows -> g_Zn (fp32) + g_hi/g_lo (bf16 split).
// One warp per row.
// ---------------------------------------------------------------------------
__global__ void __launch_bounds__(256) normalize_kernel(const float* __restrict__ z1,
                                                        const float* __restrict__ z2) {
    const int row  = blockIdx.x * 8 + (threadIdx.x >> 5);
    const int lane = threadIdx.x & 31;
    const float* src = (row < N_ROWS) ? (z1 + (size_t)row * D)
                                      : (z2 + (size_t)(row - N_ROWS) * D);
    float4 a = reinterpret_cast<const float4*>(src)[lane];
    float4 b = reinterpret_cast<const float4*>(src)[lane + 32];
    float ss = a.x*a.x + a.y*a.y + a.z*a.z + a.w*a.w
             + b.x*b.x + b.y*b.y + b.z*b.z + b.w*b.w;
    #pragma unroll
    for (int off = 16; off > 0; off >>= 1)
        ss += __shfl_xor_sync(0xffffffffu, ss, off);
    float scale = 1.0f / fmaxf(sqrtf(ss), 1e-12f);

    float v[8] = {a.x*scale, a.y*scale, a.z*scale, a.w*scale,
                  b.x*scale, b.y*scale, b.z*scale, b.w*scale};
    float* dst = g_Zn + (size_t)row * D;
    reinterpret_cast<float4*>(dst)[lane]      = make_float4(v[0], v[1], v[2], v[3]);
    reinterpret_cast<float4*>(dst)[lane + 32] = make_float4(v[4], v[5], v[6], v[7]);

    __nv_bfloat16 h[8], l[8];
    #pragma unroll
    for (int i = 0; i < 8; i++) {
        h[i] = __float2bfloat16(v[i]);
        l[i] = __float2bfloat16(v[i] - __bfloat162float(h[i]));
    }
    __nv_bfloat162* dh = reinterpret_cast<__nv_bfloat162*>(g_hi + (size_t)row * D);
    __nv_bfloat162* dl = reinterpret_cast<__nv_bfloat162*>(g_lo + (size_t)row * D);
    dh[lane * 2 + 0]        = __halves2bfloat162(h[0], h[1]);
    dh[lane * 2 + 1]        = __halves2bfloat162(h[2], h[3]);
    dh[(lane + 32) * 2 + 0] = __halves2bfloat162(h[4], h[5]);
    dh[(lane + 32) * 2 + 1] = __halves2bfloat162(h[6], h[7]);
    dl[lane * 2 + 0]        = __halves2bfloat162(l[0], l[1]);
    dl[lane * 2 + 1]        = __halves2bfloat162(l[2], l[3]);
    dl[(lane + 32) * 2 + 0] = __halves2bfloat162(l[4], l[5]);
    dl[(lane + 32) * 2 + 1] = __halves2bfloat162(l[6], l[7]);
}

// ---------------------------------------------------------------------------
// cp.async stage loader: A tile (128x32 hi+lo) and B tile (128x32 hi+lo)
// ---------------------------------------------------------------------------
__device__ __forceinline__ void load_stage(uint32_t stageAddr, int kt,
                                           int rowBase, int colBase, int tid) {
    const int kOff = kt * BK;
    #pragma unroll
    for (int i = 0; i < 4; i++) {
        const int v = i * 256 + tid;       // 1024 16B-chunks for A
        const int row = v >> 3, ch = v & 7;
        const __nv_bfloat16* g = (ch < 4) ? g_hi : g_lo;
        const void* src = g + (size_t)(rowBase + row) * D + kOff + (ch & 3) * 8;
        const uint32_t dst = stageAddr + row * 128 + ((ch ^ (row & 7)) << 4);
        CP_ASYNC16(dst, src);
    }
    #pragma unroll
    for (int i = 0; i < 4; i++) {
        const int v = i * 256 + tid;
        const int row = v >> 3, ch = v & 7;
        const __nv_bfloat16* g = (ch < 4) ? g_hi : g_lo;
        const void* src = g + (size_t)(colBase + row) * D + kOff + (ch & 3) * 8;
        const uint32_t dst = stageAddr + OFF_B + row * 128 + ((ch ^ (row & 7)) << 4);
        CP_ASYNC16(dst, src);
    }
}

// ---------------------------------------------------------------------------
// Kernel 2: HMMA fused sim-GEMM + exp + row-sum.
// CTA (bx,by): rows [bx*128,+128) x cols [by*128,+128). 3-pass hi/lo bf16.
// 8 warps: warpM = w>>1 (0..3, 32 rows each), warpN = w&1 (0..1, 64 cols each).
// B tile is [col][k] (k-contiguous) == same layout class as A, so B fragments
// come from PLAIN ldmatrix (k-contiguous register pairs), NOT the .trans form.
// ---------------------------------------------------------------------------
__global__ void __launch_bounds__(256, 2) simsum_mma_kernel() {
    extern __shared__ char smem[];
    const uint32_t smem_u32 = smem_to_u32(smem);
    const int tid     = threadIdx.x;
    const int rowBase = blockIdx.x * BM;
    const int colBase = blockIdx.y * BN;

    const int lane  = tid & 31;
    const int w     = tid >> 5;
    const int warpM = w >> 1;
    const int warpN = w & 1;

    // ldmatrix lane->address precompute
    // A (m16k16 frag): lanes 0-15 rows 0..15 (k0-7), lanes 16-31 rows 0..15 (k8-15)
    const int aRow  = warpM * 32 + (lane & 7) + ((lane >> 3) & 1) * 8;
    const int aCh   = (lane >> 4) & 1;
    const int aRm   = aRow & 7;
    // B (n8k16 frag x2 col-groups): lanes 0-7 cols0-7 k0-7; 8-15 cols0-7 k8-15;
    // 16-23 cols8-15 k0-7; 24-31 cols8-15 k8-15.
    const int bRow  = warpN * 64 + (lane & 7) + ((lane >> 4) & 1) * 8;
    const int bCh   = (lane >> 3) & 1;
    const int bRm   = bRow & 7;

    float acc[2][8][4];
    #pragma unroll
    for (int mt = 0; mt < 2; mt++)
        #pragma unroll
        for (int nt = 0; nt < 8; nt++)
            #pragma unroll
            for (int r = 0; r < 4; r++) acc[mt][nt][r] = 0.0f;

    load_stage(smem_u32, 0, rowBase, colBase, tid);
    CP_COMMIT();

    #pragma unroll 1
    for (int kt = 0; kt < NKT; kt++) {
        const uint32_t stage = smem_u32 + (uint32_t)(kt & 1) * STAGE_BYTES;
        if (kt + 1 < NKT) {
            load_stage(smem_u32 + (uint32_t)((kt + 1) & 1) * STAGE_BYTES,
                       kt + 1, rowBase, colBase, tid);
            CP_COMMIT();
            CP_WAIT(1);
        } else {
            CP_WAIT(0);
        }
        __syncthreads();

        const uint32_t aBase = stage;
        const uint32_t bBase = stage + OFF_B;
        const int aRowByte[2] = {aRow * 128, (aRow + 16) * 128};
        const int bRowByte[4] = {bRow * 128, (bRow + 16) * 128,
                                 (bRow + 32) * 128, (bRow + 48) * 128};

        #pragma unroll
        for (int s = 0; s < 2; s++) {
            uint32_t ah[2][4], al[2][4], bh[4][4], bl[4][4];
            // A hi, B hi
            #pragma unroll
            for (int mt = 0; mt < 2; mt++)
                ldsm4(ah[mt], swadr(aBase, aRowByte[mt], aRm, 2 * s + aCh));
            #pragma unroll
            for (int p = 0; p < 4; p++)
                ldsm4(bh[p], swadr(bBase, bRowByte[p], bRm, 2 * s + bCh));
            // pass hh
            #pragma unroll
            for (int mt = 0; mt < 2; mt++)
                #pragma unroll
                for (int nt = 0; nt < 8; nt++)
                    mma16816(acc[mt][nt], ah[mt], bh[nt >> 1][(nt & 1) * 2],
                             bh[nt >> 1][(nt & 1) * 2 + 1]);
            // B lo, pass hl
            #pragma unroll
            for (int p = 0; p < 4; p++)
                ldsm4(bl[p], swadr(bBase, bRowByte[p], bRm, 4 + 2 * s + bCh));
            #pragma unroll
            for (int mt = 0; mt < 2; mt++)
                #pragma unroll
                for (int nt = 0; nt < 8; nt++)
                    mma16816(acc[mt][nt], ah[mt], bl[nt >> 1][(nt & 1) * 2],
                             bl[nt >> 1][(nt & 1) * 2 + 1]);
            // A lo, pass lh
            #pragma unroll
            for (int mt = 0; mt < 2; mt++)
                ldsm4(al[mt], swadr(aBase, aRowByte[mt], aRm, 4 + 2 * s + aCh));
            #pragma unroll
            for (int mt = 0; mt < 2; mt++)
                #pragma unroll
                for (int nt = 0; nt < 8; nt++)
                    mma16816(acc[mt][nt], al[mt], bh[nt >> 1][(nt & 1) * 2],
                             bh[nt >> 1][(nt & 1) * 2 + 1]);
        }
        __syncthreads();
    }

    // Epilogue: exp(acc/T), row-sum. acc[mt][nt] c0/c1 -> row warpM*32+mt*16+(lane>>2),
    // c2/c3 -> row +8; cols nt*8 + (lane&3)*2 (+1).
    const float invT = c_invT;
    float* scratch = reinterpret_cast<float*>(smem);  // reuse stage smem [2][128]

    float s0[2] = {0.0f, 0.0f}, s1[2] = {0.0f, 0.0f};
    #pragma unroll
    for (int mt = 0; mt < 2; mt++)
        #pragma unroll
        for (int nt = 0; nt < 8; nt++) {
            s0[mt] += __expf(acc[mt][nt][0] * invT) + __expf(acc[mt][nt][1] * invT);
            s1[mt] += __expf(acc[mt][nt][2] * invT) + __expf(acc[mt][nt][3] * invT);
        }
    #pragma unroll
    for (int off = 1; off <= 2; off <<= 1) {
        #pragma unroll
        for (int mt = 0; mt < 2; mt++) {
            s0[mt] += __shfl_xor_sync(0xffffffffu, s0[mt], off);
            s1[mt] += __shfl_xor_sync(0xffffffffu, s1[mt], off);
        }
    }
    if ((lane & 3) == 0) {
        const int r8 = lane >> 2;
        #pragma unroll
        for (int mt = 0; mt < 2; mt++) {
            scratch[warpN * 128 + warpM * 32 + mt * 16 + 0 + r8] = s0[mt];
            scratch[warpN * 128 + warpM * 32 + mt * 16 + 8 + r8] = s1[mt];
        }
    }
    __syncthreads();
    if (tid < 128) {
        const float p = scratch[tid] + scratch[128 + tid];
        g_partial[(size_t)(rowBase + tid) * NCOLTILES + blockIdx.y] = p;
    }
}

// ---------------------------------------------------------------------------
// Kernel 3: per-row loss. One warp per row.
// loss_i = log(total_i - exp(dot(z1n_i, z2n_0)/T)) - dot(z1n_i, z2n_i)/T
// ---------------------------------------------------------------------------
__global__ void __launch_bounds__(256) loss_kernel() {
    const int row  = blockIdx.x * 8 + (threadIdx.x >> 5);
    const int lane = threadIdx.x & 31;

    float total = g_partial[(size_t)row * NCOLTILES + lane]
                + g_partial[(size_t)row * NCOLTILES + lane + 32];

    const float4* z1r = reinterpret_cast<const float4*>(g_Zn + (size_t)row * D);
    const float4* z2r = reinterpret_cast<const float4*>(g_Zn + (size_t)(N_ROWS + row) * D);
    const float4* z20 = reinterpret_cast<const float4*>(g_Zn + (size_t)N_ROWS * D);

    float dp = 0.0f, d0 = 0.0f;
    #pragma unroll
    for (int h = 0; h < 2; h++) {
        float4 a = z1r[lane + h * 32];
        float4 b = z2r[lane + h * 32];
        float4 c = z20[lane + h * 32];
        dp += a.x*b.x + a.y*b.y + a.z*b.z + a.w*b.w;
        d0 += a.x*c.x + a.y*c.y + a.z*c.z + a.w*c.w;
    }
    #pragma unroll
    for (int off = 16; off > 0; off >>= 1) {
        total += __shfl_xor_sync(0xffffffffu, total, off);
        dp    += __shfl_xor_sync(0xffffffffu, dp, off);
        d0    += __shfl_xor_sync(0xffffffffu, d0, off);
    }
    if (lane == 0) {
        const float invT = c_invT;
        float sum_negs = total - __expf(d0 * invT);
        g_loss[row] = logf(sum_negs) - dp * invT;
    }
}

// ---------------------------------------------------------------------------
// Kernel 4: mean over 4096 rows -> d_out[0]
// ---------------------------------------------------------------------------
__global__ void __launch_bounds__(256) reduce_kernel(float* __restrict__ out) {
    __shared__ float s[256];
    float v = 0.0f;
    const float4* gl = reinterpret_cast<const float4*>(g_loss);
    for (int i = threadIdx.x; i < N_ROWS / 4; i += 256) {
        float4 t = gl[i];
        v += t.x + t.y + t.z + t.w;
    }
    s[threadIdx.x] = v;
    __syncthreads();
    #pragma unroll
    for (int stride = 128; stride > 0; stride >>= 1) {
        if (threadIdx.x < stride) s[threadIdx.x] += s[threadIdx.x + stride];
        __syncthreads();
    }
    if (threadIdx.x == 0) out[0] = s[0] * (1.0f / N_ROWS);
}

// ---------------------------------------------------------------------------
extern "C" void kernel_launch(void* const* d_in, const int* in_sizes, int n_in,
                              void* d_out, int out_size) {
    const float* z1 = (const float*)d_in[0];
    const float* z2 = (const float*)d_in[1];
    float* out = (float*)d_out;

    cudaFuncSetAttribute(simsum_mma_kernel,
                         cudaFuncAttributeMaxDynamicSharedMemorySize, SMEM_TOTAL);

    normalize_kernel<<<TWO_N / 8, 256>>>(z1, z2);
    dim3 grid(N_ROWS / BM, TWO_N / BN);
    simsum_mma_kernel<<<grid, 256, SMEM_TOTAL>>>();
    loss_kernel<<<N_ROWS / 8, 256>>>();
    reduce_kernel<<<1, 256>>>(out);
}

// round 5
// speedup vs baseline: 6.3971x; 2.0493x over previous
#include <cuda_runtime.h>
#include <cuda_bf16.h>
#include <math.h>
#include <stdint.h>

#define N_ROWS 4096
#define D      256
#define TWO_N  8192
#define BM 128
#define BN 128
#define BK 32
#define NKT (D / BK)              // 8 k-chunks
#define NCOLTILES 64              // one partial per (row, 128-col tile)

__device__ __constant__ float c_invT = 14.285714285714286f; // 1/0.07

// Scratch (device globals; no allocation anywhere)
__device__ float          g_Zn[TWO_N * D];       // normalized fp32 (exact loss terms)
__device__ __nv_bfloat16  g_hi[TWO_N * D];       // bf16 rounded normalized
__device__ float          g_partial[N_ROWS * NCOLTILES];
__device__ float          g_loss[N_ROWS];

// ---------------------------------------------------------------------------
// PTX helpers (all arch-agnostic: sm_80+ baseline instructions only)
// ---------------------------------------------------------------------------
__device__ __forceinline__ uint32_t smem_to_u32(const void* p) {
    uint32_t a;
    asm("{ .reg .u64 t; cvta.to.shared.u64 t, %1; cvt.u32.u64 %0, t; }" : "=r"(a) : "l"(p));
    return a;
}
#define CP_ASYNC16(dst, src) \
    asm volatile("cp.async.cg.shared.global [%0], [%1], 16;" :: "r"(dst), "l"(src))
#define CP_COMMIT() asm volatile("cp.async.commit_group;" ::: "memory")
#define CP_WAIT(n)  asm volatile("cp.async.wait_group %0;" :: "n"(n) : "memory")

__device__ __forceinline__ void ldsm4(uint32_t* r, uint32_t addr) {
    asm volatile("ldmatrix.sync.aligned.m8n8.x4.shared.b16 {%0,%1,%2,%3}, [%4];"
        : "=r"(r[0]), "=r"(r[1]), "=r"(r[2]), "=r"(r[3]) : "r"(addr));
}
__device__ __forceinline__ void mma16816(float* c, const uint32_t* a,
                                         uint32_t b0, uint32_t b1) {
    asm volatile("mma.sync.aligned.m16n8k16.row.col.f32.bf16.bf16.f32 "
        "{%0,%1,%2,%3}, {%4,%5,%6,%7}, {%8,%9}, {%0,%1,%2,%3};"
        : "+f"(c[0]), "+f"(c[1]), "+f"(c[2]), "+f"(c[3])
        : "r"(a[0]), "r"(a[1]), "r"(a[2]), "r"(a[3]), "r"(b0), "r"(b1));
}

// Stage layout: 128 rows x 128 bytes (8 x 16B chunks per row).
// Chunks 0-3 = A tile (32 bf16 of k), chunks 4-7 = B tile (same row index =
// local col). Full 3-bit XOR swizzle: slot = chunkIdx ^ (row & 7) -> the 8
// pointers of every ldmatrix phase cover all 8 16B-banks (conflict-free).
__device__ __forceinline__ uint32_t swadr(uint32_t base, int rowByte, int rm, int ch) {
    return base + rowByte + ((ch ^ rm) << 4);
}

#define STAGE_BYTES 16384
#define SMEM_TOTAL  (2 * STAGE_BYTES)   // 32 KB

// ---------------------------------------------------------------------------
// Kernel 1: L2-normalize rows -> g_Zn (fp32) + g_hi (bf16). One warp per row.
// ---------------------------------------------------------------------------
__global__ void __launch_bounds__(256) normalize_kernel(const float* __restrict__ z1,
                                                        const float* __restrict__ z2) {
    const int row  = blockIdx.x * 8 + (threadIdx.x >> 5);
    const int lane = threadIdx.x & 31;
    const float* src = (row < N_ROWS) ? (z1 + (size_t)row * D)
                                      : (z2 + (size_t)(row - N_ROWS) * D);
    float4 a = reinterpret_cast<const float4*>(src)[lane];
    float4 b = reinterpret_cast<const float4*>(src)[lane + 32];
    float ss = a.x*a.x + a.y*a.y + a.z*a.z + a.w*a.w
             + b.x*b.x + b.y*b.y + b.z*b.z + b.w*b.w;
    #pragma unroll
    for (int off = 16; off > 0; off >>= 1)
        ss += __shfl_xor_sync(0xffffffffu, ss, off);
    float scale = 1.0f / fmaxf(sqrtf(ss), 1e-12f);

    float v[8] = {a.x*scale, a.y*scale, a.z*scale, a.w*scale,
                  b.x*scale, b.y*scale, b.z*scale, b.w*scale};
    float* dst = g_Zn + (size_t)row * D;
    reinterpret_cast<float4*>(dst)[lane]      = make_float4(v[0], v[1], v[2], v[3]);
    reinterpret_cast<float4*>(dst)[lane + 32] = make_float4(v[4], v[5], v[6], v[7]);

    __nv_bfloat162* dh = reinterpret_cast<__nv_bfloat162*>(g_hi + (size_t)row * D);
    dh[lane * 2 + 0]        = __halves2bfloat162(__float2bfloat16(v[0]), __float2bfloat16(v[1]));
    dh[lane * 2 + 1]        = __halves2bfloat162(__float2bfloat16(v[2]), __float2bfloat16(v[3]));
    dh[(lane + 32) * 2 + 0] = __halves2bfloat162(__float2bfloat16(v[4]), __float2bfloat16(v[5]));
    dh[(lane + 32) * 2 + 1] = __halves2bfloat162(__float2bfloat16(v[6]), __float2bfloat16(v[7]));
}

// ---------------------------------------------------------------------------
// cp.async stage loader: A tile (128 rows x 32 bf16, chunks 0-3) and B tile
// (128 cols x 32 bf16, chunks 4-7) -> one 16KB stage. 1024 16B chunks.
// ---------------------------------------------------------------------------
__device__ __forceinline__ void load_stage(uint32_t stageAddr, int kt,
                                           int rowBase, int colBase, int tid) {
    const int kOff = kt * BK;
    #pragma unroll
    for (int i = 0; i < 4; i++) {
        const int v = i * 256 + tid;
        const int row = v >> 3, ch = v & 7;       // ch 0-3: A, 4-7: B
        const int gRow = (ch < 4) ? (rowBase + row) : (colBase + row);
        const void* src = g_hi + (size_t)gRow * D + kOff + (ch & 3) * 8;
        const uint32_t dst = stageAddr + row * 128 + ((ch ^ (row & 7)) << 4);
        CP_ASYNC16(dst, src);
    }
}

// ---------------------------------------------------------------------------
// Kernel 2: HMMA fused sim-GEMM + exp + row-sum. Single bf16 pass.
// CTA (bx,by): rows [bx*128,+128) x cols [by*128,+128).
// 8 warps: warpM = w>>1 (32 rows each), warpN = w&1 (64 cols each).
// B tile is [col][k] (k-contiguous, same layout class as A) -> plain ldmatrix.
// ---------------------------------------------------------------------------
__global__ void __launch_bounds__(256, 2) simsum_mma_kernel() {
    extern __shared__ char smem[];
    const uint32_t smem_u32 = smem_to_u32(smem);
    const int tid     = threadIdx.x;
    const int rowBase = blockIdx.x * BM;
    const int colBase = blockIdx.y * BN;

    const int lane  = tid & 31;
    const int w     = tid >> 5;
    const int warpM = w >> 1;
    const int warpN = w & 1;

    // ldmatrix lane->address precompute
    const int aRow  = warpM * 32 + (lane & 7) + ((lane >> 3) & 1) * 8;
    const int aCh   = (lane >> 4) & 1;            // k-halves 0-15 / 16-31 per s
    const int aRm   = aRow & 7;
    const int bRow  = warpN * 64 + (lane & 7) + ((lane >> 4) & 1) * 8;
    const int bCh   = (lane >> 3) & 1;
    const int bRm   = bRow & 7;

    float acc[2][8][4];
    #pragma unroll
    for (int mt = 0; mt < 2; mt++)
        #pragma unroll
        for (int nt = 0; nt < 8; nt++)
            #pragma unroll
            for (int r = 0; r < 4; r++) acc[mt][nt][r] = 0.0f;

    load_stage(smem_u32, 0, rowBase, colBase, tid);
    CP_COMMIT();

    #pragma unroll 1
    for (int kt = 0; kt < NKT; kt++) {
        const uint32_t stage = smem_u32 + (uint32_t)(kt & 1) * STAGE_BYTES;
        if (kt + 1 < NKT) {
            load_stage(smem_u32 + (uint32_t)((kt + 1) & 1) * STAGE_BYTES,
                       kt + 1, rowBase, colBase, tid);
            CP_COMMIT();
            CP_WAIT(1);
        } else {
            CP_WAIT(0);
        }
        __syncthreads();

        const int aRowByte[2] = {aRow * 128, (aRow + 16) * 128};
        const int bRowByte[4] = {bRow * 128, (bRow + 16) * 128,
                                 (bRow + 32) * 128, (bRow + 48) * 128};

        #pragma unroll
        for (int s = 0; s < 2; s++) {
            uint32_t ah[2][4], bh[4][4];
            #pragma unroll
            for (int mt = 0; mt < 2; mt++)
                ldsm4(ah[mt], swadr(stage, aRowByte[mt], aRm, 2 * s + aCh));
            #pragma unroll
            for (int p = 0; p < 4; p++)
                ldsm4(bh[p], swadr(stage, bRowByte[p], bRm, 4 + 2 * s + bCh));
            #pragma unroll
            for (int mt = 0; mt < 2; mt++)
                #pragma unroll
                for (int nt = 0; nt < 8; nt++)
                    mma16816(acc[mt][nt], ah[mt], bh[nt >> 1][(nt & 1) * 2],
                             bh[nt >> 1][(nt & 1) * 2 + 1]);
        }
        __syncthreads();
    }

    // Epilogue: exp(acc/T), row-sum across this 128-col tile.
    const float invT = c_invT;
    float* scratch = reinterpret_cast<float*>(smem);  // reuse stage smem [2][128]

    float s0[2] = {0.0f, 0.0f}, s1[2] = {0.0f, 0.0f};
    #pragma unroll
    for (int mt = 0; mt < 2; mt++)
        #pragma unroll
        for (int nt = 0; nt < 8; nt++) {
            s0[mt] += __expf(acc[mt][nt][0] * invT) + __expf(acc[mt][nt][1] * invT);
            s1[mt] += __expf(acc[mt][nt][2] * invT) + __expf(acc[mt][nt][3] * invT);
        }
    #pragma unroll
    for (int off = 1; off <= 2; off <<= 1) {
        #pragma unroll
        for (int mt = 0; mt < 2; mt++) {
            s0[mt] += __shfl_xor_sync(0xffffffffu, s0[mt], off);
            s1[mt] += __shfl_xor_sync(0xffffffffu, s1[mt], off);
        }
    }
    if ((lane & 3) == 0) {
        const int r8 = lane >> 2;
        #pragma unroll
        for (int mt = 0; mt < 2; mt++) {
            scratch[warpN * 128 + warpM * 32 + mt * 16 + 0 + r8] = s0[mt];
            scratch[warpN * 128 + warpM * 32 + mt * 16 + 8 + r8] = s1[mt];
        }
    }
    __syncthreads();
    if (tid < 128) {
        const float p = scratch[tid] + scratch[128 + tid];
        g_partial[(size_t)(rowBase + tid) * NCOLTILES + blockIdx.y] = p;
    }
}

// ---------------------------------------------------------------------------
// Kernel 3: per-row loss. One warp per row. Exact fp32 correction terms.
// loss_i = log(total_i - exp(dot(z1n_i, z2n_0)/T)) - dot(z1n_i, z2n_i)/T
// ---------------------------------------------------------------------------
__global__ void __launch_bounds__(256) loss_kernel() {
    const int row  = blockIdx.x * 8 + (threadIdx.x >> 5);
    const int lane = threadIdx.x & 31;

    float total = g_partial[(size_t)row * NCOLTILES + lane]
                + g_partial[(size_t)row * NCOLTILES + lane + 32];

    const float4* z1r = reinterpret_cast<const float4*>(g_Zn + (size_t)row * D);
    const float4* z2r = reinterpret_cast<const float4*>(g_Zn + (size_t)(N_ROWS + row) * D);
    const float4* z20 = reinterpret_cast<const float4*>(g_Zn + (size_t)N_ROWS * D);

    float dp = 0.0f, d0 = 0.0f;
    #pragma unroll
    for (int h = 0; h < 2; h++) {
        float4 a = z1r[lane + h * 32];
        float4 b = z2r[lane + h * 32];
        float4 c = z20[lane + h * 32];
        dp += a.x*b.x + a.y*b.y + a.z*b.z + a.w*b.w;
        d0 += a.x*c.x + a.y*c.y + a.z*c.z + a.w*c.w;
    }
    #pragma unroll
    for (int off = 16; off > 0; off >>= 1) {
        total += __shfl_xor_sync(0xffffffffu, total, off);
        dp    += __shfl_xor_sync(0xffffffffu, dp, off);
        d0    += __shfl_xor_sync(0xffffffffu, d0, off);
    }
    if (lane == 0) {
        const float invT = c_invT;
        float sum_negs = total - __expf(d0 * invT);
        g_loss[row] = logf(sum_negs) - dp * invT;
    }
}

// ---------------------------------------------------------------------------
// Kernel 4: mean over 4096 rows -> d_out[0]
// ---------------------------------------------------------------------------
__global__ void __launch_bounds__(256) reduce_kernel(float* __restrict__ out) {
    __shared__ float s[256];
    float v = 0.0f;
    const float4* gl = reinterpret_cast<const float4*>(g_loss);
    for (int i = threadIdx.x; i < N_ROWS / 4; i += 256) {
        float4 t = gl[i];
        v += t.x + t.y + t.z + t.w;
    }
    s[threadIdx.x] = v;
    __syncthreads();
    #pragma unroll
    for (int stride = 128; stride > 0; stride >>= 1) {
        if (threadIdx.x < stride) s[threadIdx.x] += s[threadIdx.x + stride];
        __syncthreads();
    }
    if (threadIdx.x == 0) out[0] = s[0] * (1.0f / N_ROWS);
}

// ---------------------------------------------------------------------------
extern "C" void kernel_launch(void* const* d_in, const int* in_sizes, int n_in,
                              void* d_out, int out_size) {
    const float* z1 = (const float*)d_in[0];
    const float* z2 = (const float*)d_in[1];
    float* out = (float*)d_out;

    cudaFuncSetAttribute(simsum_mma_kernel,
                         cudaFuncAttributeMaxDynamicSharedMemorySize, SMEM_TOTAL);

    normalize_kernel<<<TWO_N / 8, 256>>>(z1, z2);
    dim3 grid(N_ROWS / BM, TWO_N / BN);
    simsum_mma_kernel<<<grid, 256, SMEM_TOTAL>>>();
    loss_kernel<<<N_ROWS / 8, 256>>>();
    reduce_kernel<<<1, 256>>>(out);
}

// round 6
// speedup vs baseline: 7.5477x; 1.1799x over previous
#include <cuda_runtime.h>
#include <cuda_bf16.h>
#include <math.h>
#include <stdint.h>

#define N_ROWS 4096
#define D      256
#define TWO_N  8192
#define BM 128
#define BN 128
#define BK 32
#define NKT (D / BK)              // 8 k-chunks
#define NCOLTILES 64              // one partial per (row, 128-col tile)
#define NLOSSBLK (N_ROWS / 8)     // 512 loss blocks

__device__ __constant__ float c_invT = 14.285714285714286f; // 1/0.07

// Scratch (device globals; no allocation anywhere)
__device__ float          g_Zn[TWO_N * D];       // normalized fp32 (exact loss terms)
__device__ __nv_bfloat16  g_hi[TWO_N * D];       // bf16 rounded normalized
__device__ float          g_partial[N_ROWS * NCOLTILES];
__device__ float          g_blocksum[NLOSSBLK];
__device__ int            g_counter = 0;

// ---------------------------------------------------------------------------
// PTX helpers (all arch-agnostic: sm_80+ baseline instructions only)
// ---------------------------------------------------------------------------
__device__ __forceinline__ uint32_t smem_to_u32(const void* p) {
    uint32_t a;
    asm("{ .reg .u64 t; cvta.to.shared.u64 t, %1; cvt.u32.u64 %0, t; }" : "=r"(a) : "l"(p));
    return a;
}
#define CP_ASYNC16(dst, src) \
    asm volatile("cp.async.cg.shared.global [%0], [%1], 16;" :: "r"(dst), "l"(src))
#define CP_COMMIT() asm volatile("cp.async.commit_group;" ::: "memory")
#define CP_WAIT(n)  asm volatile("cp.async.wait_group %0;" :: "n"(n) : "memory")

__device__ __forceinline__ void ldsm4(uint32_t* r, uint32_t addr) {
    asm volatile("ldmatrix.sync.aligned.m8n8.x4.shared.b16 {%0,%1,%2,%3}, [%4];"
        : "=r"(r[0]), "=r"(r[1]), "=r"(r[2]), "=r"(r[3]) : "r"(addr));
}
__device__ __forceinline__ void mma16816(float* c, const uint32_t* a,
                                         uint32_t b0, uint32_t b1) {
    asm volatile("mma.sync.aligned.m16n8k16.row.col.f32.bf16.bf16.f32 "
        "{%0,%1,%2,%3}, {%4,%5,%6,%7}, {%8,%9}, {%0,%1,%2,%3};"
        : "+f"(c[0]), "+f"(c[1]), "+f"(c[2]), "+f"(c[3])
        : "r"(a[0]), "r"(a[1]), "r"(a[2]), "r"(a[3]), "r"(b0), "r"(b1));
}

// Stage layout: 128 rows x 128 bytes (8 x 16B chunks per row).
// Chunks 0-3 = A tile (32 bf16 of k), chunks 4-7 = B tile (row index = local
// col). Full 3-bit XOR swizzle: slot = chunkIdx ^ (row & 7) -> conflict-free.
__device__ __forceinline__ uint32_t swadr(uint32_t base, int rowByte, int rm, int ch) {
    return base + rowByte + ((ch ^ rm) << 4);
}

#define STAGE_BYTES 16384
#define SMEM_TOTAL  (2 * STAGE_BYTES)   // 32 KB

// ---------------------------------------------------------------------------
// Kernel 1: L2-normalize rows -> g_Zn (fp32) + g_hi (bf16). One warp per row.
// ---------------------------------------------------------------------------
__global__ void __launch_bounds__(256) normalize_kernel(const float* __restrict__ z1,
                                                        const float* __restrict__ z2) {
    const int row  = blockIdx.x * 8 + (threadIdx.x >> 5);
    const int lane = threadIdx.x & 31;
    const float* src = (row < N_ROWS) ? (z1 + (size_t)row * D)
                                      : (z2 + (size_t)(row - N_ROWS) * D);
    float4 a = reinterpret_cast<const float4*>(src)[lane];
    float4 b = reinterpret_cast<const float4*>(src)[lane + 32];
    float ss = a.x*a.x + a.y*a.y + a.z*a.z + a.w*a.w
             + b.x*b.x + b.y*b.y + b.z*b.z + b.w*b.w;
    #pragma unroll
    for (int off = 16; off > 0; off >>= 1)
        ss += __shfl_xor_sync(0xffffffffu, ss, off);
    float scale = 1.0f / fmaxf(sqrtf(ss), 1e-12f);

    float v[8] = {a.x*scale, a.y*scale, a.z*scale, a.w*scale,
                  b.x*scale, b.y*scale, b.z*scale, b.w*scale};
    float* dst = g_Zn + (size_t)row * D;
    reinterpret_cast<float4*>(dst)[lane]      = make_float4(v[0], v[1], v[2], v[3]);
    reinterpret_cast<float4*>(dst)[lane + 32] = make_float4(v[4], v[5], v[6], v[7]);

    __nv_bfloat162* dh = reinterpret_cast<__nv_bfloat162*>(g_hi + (size_t)row * D);
    dh[lane * 2 + 0]        = __halves2bfloat162(__float2bfloat16(v[0]), __float2bfloat16(v[1]));
    dh[lane * 2 + 1]        = __halves2bfloat162(__float2bfloat16(v[2]), __float2bfloat16(v[3]));
    dh[(lane + 32) * 2 + 0] = __halves2bfloat162(__float2bfloat16(v[4]), __float2bfloat16(v[5]));
    dh[(lane + 32) * 2 + 1] = __halves2bfloat162(__float2bfloat16(v[6]), __float2bfloat16(v[7]));
}

// ---------------------------------------------------------------------------
// cp.async stage loader: A tile (128 rows x 32 bf16, chunks 0-3) + B tile
// (128 cols x 32 bf16, chunks 4-7) -> one 16KB stage.
// ---------------------------------------------------------------------------
__device__ __forceinline__ void load_stage(uint32_t stageAddr, int kt,
                                           int rowBase, int colBase, int tid) {
    const int kOff = kt * BK;
    #pragma unroll
    for (int i = 0; i < 4; i++) {
        const int v = i * 256 + tid;
        const int row = v >> 3, ch = v & 7;       // ch 0-3: A, 4-7: B
        const int gRow = (ch < 4) ? (rowBase + row) : (colBase + row);
        const void* src = g_hi + (size_t)gRow * D + kOff + (ch & 3) * 8;
        const uint32_t dst = stageAddr + row * 128 + ((ch ^ (row & 7)) << 4);
        CP_ASYNC16(dst, src);
    }
}

// ---------------------------------------------------------------------------
// Kernel 2: HMMA fused sim-GEMM + exp + row/col sums, exploiting symmetry of
// the Z1*Z1^T half.
// Grid: 1552 1D blocks.
//   b <  1024: right half (cols 4096..8192): bx=b>>5, colTile=32+(b&31), rowsum only.
//   b >= 1024: triangular tiles of the symmetric half, colTile<=bx.
//              off-diagonal: rowsum -> slot colTile AND colsum -> slot bx.
// ---------------------------------------------------------------------------
__global__ void __launch_bounds__(256, 2) simsum_mma_kernel() {
    extern __shared__ char smem[];
    const uint32_t smem_u32 = smem_to_u32(smem);
    const int tid = threadIdx.x;

    int bx, colTile;
    bool sym = false;
    {
        const int b = blockIdx.x;
        if (b < 1024) {
            bx = b >> 5;
            colTile = 32 + (b & 31);
        } else {
            const int t = b - 1024;
            int e = (int)((sqrtf(8.0f * t + 1.0f) - 1.0f) * 0.5f);
            while ((e + 1) * (e + 2) / 2 <= t) e++;
            while (e * (e + 1) / 2 > t) e--;
            bx = e;
            colTile = t - e * (e + 1) / 2;
            sym = (colTile != bx);
        }
    }
    const int rowBase = bx * BM;
    const int colBase = colTile * BN;

    const int lane  = tid & 31;
    const int w     = tid >> 5;
    const int warpM = w >> 1;
    const int warpN = w & 1;

    // ldmatrix lane->address precompute
    const int aRow  = warpM * 32 + (lane & 7) + ((lane >> 3) & 1) * 8;
    const int aCh   = (lane >> 4) & 1;
    const int aRm   = aRow & 7;
    const int bRow  = warpN * 64 + (lane & 7) + ((lane >> 4) & 1) * 8;
    const int bCh   = (lane >> 3) & 1;
    const int bRm   = bRow & 7;

    float acc[2][8][4];
    #pragma unroll
    for (int mt = 0; mt < 2; mt++)
        #pragma unroll
        for (int nt = 0; nt < 8; nt++)
            #pragma unroll
            for (int r = 0; r < 4; r++) acc[mt][nt][r] = 0.0f;

    load_stage(smem_u32, 0, rowBase, colBase, tid);
    CP_COMMIT();

    #pragma unroll 1
    for (int kt = 0; kt < NKT; kt++) {
        const uint32_t stage = smem_u32 + (uint32_t)(kt & 1) * STAGE_BYTES;
        if (kt + 1 < NKT) {
            load_stage(smem_u32 + (uint32_t)((kt + 1) & 1) * STAGE_BYTES,
                       kt + 1, rowBase, colBase, tid);
            CP_COMMIT();
            CP_WAIT(1);
        } else {
            CP_WAIT(0);
        }
        __syncthreads();

        const int aRowByte[2] = {aRow * 128, (aRow + 16) * 128};
        const int bRowByte[4] = {bRow * 128, (bRow + 16) * 128,
                                 (bRow + 32) * 128, (bRow + 48) * 128};

        #pragma unroll
        for (int s = 0; s < 2; s++) {
            uint32_t ah[2][4], bh[4][4];
            #pragma unroll
            for (int mt = 0; mt < 2; mt++)
                ldsm4(ah[mt], swadr(stage, aRowByte[mt], aRm, 2 * s + aCh));
            #pragma unroll
            for (int p = 0; p < 4; p++)
                ldsm4(bh[p], swadr(stage, bRowByte[p], bRm, 4 + 2 * s + bCh));
            #pragma unroll
            for (int mt = 0; mt < 2; mt++)
                #pragma unroll
                for (int nt = 0; nt < 8; nt++)
                    mma16816(acc[mt][nt], ah[mt], bh[nt >> 1][(nt & 1) * 2],
                             bh[nt >> 1][(nt & 1) * 2 + 1]);
        }
        __syncthreads();
    }

    // ---------------- Epilogue ----------------
    // acc[mt][nt] regs: c0/c1 -> row warpM*32+mt*16+(lane>>2), cols nt*8+(lane&3)*2 (+1)
    //                   c2/c3 -> row +8, same cols.
    const float invT = c_invT;
    float* rowScratch = reinterpret_cast<float*>(smem);         // [2][128]
    float* colScratch = reinterpret_cast<float*>(smem) + 256;   // [2][4][64]

    float rs0[2] = {0.0f, 0.0f}, rs1[2] = {0.0f, 0.0f};
    float cs[16];
    #pragma unroll
    for (int i = 0; i < 16; i++) cs[i] = 0.0f;

    #pragma unroll
    for (int mt = 0; mt < 2; mt++)
        #pragma unroll
        for (int nt = 0; nt < 8; nt++) {
            const float e0 = __expf(acc[mt][nt][0] * invT);
            const float e1 = __expf(acc[mt][nt][1] * invT);
            const float e2 = __expf(acc[mt][nt][2] * invT);
            const float e3 = __expf(acc[mt][nt][3] * invT);
            rs0[mt] += e0 + e1;
            rs1[mt] += e2 + e3;
            cs[nt * 2 + 0] += e0 + e2;
            cs[nt * 2 + 1] += e1 + e3;
        }

    // Row reduce: sum over the 4 lanes sharing lane>>2 (different columns)
    #pragma unroll
    for (int off = 1; off <= 2; off <<= 1) {
        #pragma unroll
        for (int mt = 0; mt < 2; mt++) {
            rs0[mt] += __shfl_xor_sync(0xffffffffu, rs0[mt], off);
            rs1[mt] += __shfl_xor_sync(0xffffffffu, rs1[mt], off);
        }
    }
    if ((lane & 3) == 0) {
        const int r8 = lane >> 2;
        #pragma unroll
        for (int mt = 0; mt < 2; mt++) {
            rowScratch[warpN * 128 + warpM * 32 + mt * 16 + 0 + r8] = rs0[mt];
            rowScratch[warpN * 128 + warpM * 32 + mt * 16 + 8 + r8] = rs1[mt];
        }
    }

    if (sym) {
        // Col reduce: sum over the 8 lanes sharing lane&3 (different rows)
        #pragma unroll
        for (int i = 0; i < 16; i++) {
            #pragma unroll
            for (int off = 4; off <= 16; off <<= 1)
                cs[i] += __shfl_xor_sync(0xffffffffu, cs[i], off);
        }
        if (lane < 4) {
            #pragma unroll
            for (int nt = 0; nt < 8; nt++) {
                colScratch[(warpN * 4 + warpM) * 64 + nt * 8 + lane * 2 + 0] = cs[nt * 2 + 0];
                colScratch[(warpN * 4 + warpM) * 64 + nt * 8 + lane * 2 + 1] = cs[nt * 2 + 1];
            }
        }
    }
    __syncthreads();

    if (tid < 128) {
        const float p = rowScratch[tid] + rowScratch[128 + tid];
        g_partial[(size_t)(rowBase + tid) * NCOLTILES + colTile] = p;
        if (sym) {
            const int wn = tid >> 6, ix = tid & 63;
            float c = colScratch[(wn * 4 + 0) * 64 + ix] + colScratch[(wn * 4 + 1) * 64 + ix]
                    + colScratch[(wn * 4 + 2) * 64 + ix] + colScratch[(wn * 4 + 3) * 64 + ix];
            g_partial[(size_t)(colBase + tid) * NCOLTILES + bx] = c;
        }
    }
}

// ---------------------------------------------------------------------------
// Kernel 3: per-row loss + grid-wide mean (last-block pattern, deterministic).
// loss_i = log(total_i - exp(dot(z1n_i, z2n_0)/T)) - dot(z1n_i, z2n_i)/T
// ---------------------------------------------------------------------------
__global__ void __launch_bounds__(256) loss_reduce_kernel(float* __restrict__ out) {
    __shared__ float warpLoss[8];
    __shared__ int   isLast;
    const int bid  = blockIdx.x;
    const int row  = bid * 8 + (threadIdx.x >> 5);
    const int lane = threadIdx.x & 31;

    float total = g_partial[(size_t)row * NCOLTILES + lane]
                + g_partial[(size_t)row * NCOLTILES + lane + 32];

    const float4* z1r = reinterpret_cast<const float4*>(g_Zn + (size_t)row * D);
    const float4* z2r = reinterpret_cast<const float4*>(g_Zn + (size_t)(N_ROWS + row) * D);
    const float4* z20 = reinterpret_cast<const float4*>(g_Zn + (size_t)N_ROWS * D);

    float dp = 0.0f, d0 = 0.0f;
    #pragma unroll
    for (int h = 0; h < 2; h++) {
        float4 a = z1r[lane + h * 32];
        float4 b = z2r[lane + h * 32];
        float4 c = z20[lane + h * 32];
        dp += a.x*b.x + a.y*b.y + a.z*b.z + a.w*b.w;
        d0 += a.x*c.x + a.y*c.y + a.z*c.z + a.w*c.w;
    }
    #pragma unroll
    for (int off = 16; off > 0; off >>= 1) {
        total += __shfl_xor_sync(0xffffffffu, total, off);
        dp    += __shfl_xor_sync(0xffffffffu, dp, off);
        d0    += __shfl_xor_sync(0xffffffffu, d0, off);
    }
    if (lane == 0) {
        const float invT = c_invT;
        float sum_negs = total - __expf(d0 * invT);
        warpLoss[threadIdx.x >> 5] = logf(sum_negs) - dp * invT;
    }
    __syncthreads();

    if (threadIdx.x == 0) {
        float bs = 0.0f;
        #pragma unroll
        for (int i = 0; i < 8; i++) bs += warpLoss[i];
        g_blocksum[bid] = bs;
        __threadfence();
        int old = atomicAdd(&g_counter, 1);
        isLast = (old == NLOSSBLK - 1);
    }
    __syncthreads();

    if (isLast) {
        __shared__ float s[256];
        // each thread reads 2 of the 512 block sums (bypass L1: other-SM writes)
        float v = 0.0f;
        #pragma unroll
        for (int h = 0; h < 2; h++) {
            float t;
            asm volatile("ld.global.cg.f32 %0, [%1];" : "=f"(t)
                         : "l"(g_blocksum + threadIdx.x + h * 256));
            v += t;
        }
        s[threadIdx.x] = v;
        __syncthreads();
        #pragma unroll
        for (int stride = 128; stride > 0; stride >>= 1) {
            if (threadIdx.x < stride) s[threadIdx.x] += s[threadIdx.x + stride];
            __syncthreads();
        }
        if (threadIdx.x == 0) {
            out[0] = s[0] * (1.0f / N_ROWS);
            g_counter = 0;   // reset for next graph replay
        }
    }
}

// ---------------------------------------------------------------------------
extern "C" void kernel_launch(void* const* d_in, const int* in_sizes, int n_in,
                              void* d_out, int out_size) {
    const float* z1 = (const float*)d_in[0];
    const float* z2 = (const float*)d_in[1];
    float* out = (float*)d_out;

    cudaFuncSetAttribute(simsum_mma_kernel,
                         cudaFuncAttributeMaxDynamicSharedMemorySize, SMEM_TOTAL);

    normalize_kernel<<<TWO_N / 8, 256>>>(z1, z2);
    simsum_mma_kernel<<<1552, 256, SMEM_TOTAL>>>();
    loss_reduce_kernel<<<NLOSSBLK, 256>>>(out);
}

// round 7
// speedup vs baseline: 8.2788x; 1.0969x over previous
#include <cuda_runtime.h>
#include <cuda_bf16.h>
#include <math.h>
#include <stdint.h>

#define N_ROWS 4096
#define D      256
#define TWO_N  8192
#define BM 128
#define BN 128
#define BK 32
#define NKT (D / BK)              // 8 k-chunks
#define NCOLTILES 64
#define NLOSSBLK (N_ROWS / 8)     // 512 loss blocks
#define NTILES 1552
#define GRID_GEMM 296             // 2 CTAs per SM, persistent

// exp(x/T) = 2^(x * invT * log2(e));  invT*log2e = 14.285714 * 1.4426950
__device__ __constant__ float c_l2T  = 20.609929f;
__device__ __constant__ float c_invT = 14.285714285714286f;

// Scratch (device globals; no allocation anywhere)
__device__ __nv_bfloat16  g_hi[TWO_N * D];       // bf16 normalized
__device__ float          g_partial[N_ROWS * NCOLTILES];
__device__ float          g_blocksum[NLOSSBLK];
__device__ int            g_counter = 0;

// ---------------------------------------------------------------------------
// PTX helpers (sm_80+ baseline only)
// ---------------------------------------------------------------------------
__device__ __forceinline__ uint32_t smem_to_u32(const void* p) {
    uint32_t a;
    asm("{ .reg .u64 t; cvta.to.shared.u64 t, %1; cvt.u32.u64 %0, t; }" : "=r"(a) : "l"(p));
    return a;
}
__device__ __forceinline__ float ex2(float x) {
    float r;
    asm("ex2.approx.ftz.f32 %0, %1;" : "=f"(r) : "f"(x));
    return r;
}
#define CP_ASYNC16(dst, src) \
    asm volatile("cp.async.cg.shared.global [%0], [%1], 16;" :: "r"(dst), "l"(src))
#define CP_COMMIT() asm volatile("cp.async.commit_group;" ::: "memory")
#define CP_WAIT(n)  asm volatile("cp.async.wait_group %0;" :: "n"(n) : "memory")

__device__ __forceinline__ void ldsm4(uint32_t* r, uint32_t addr) {
    asm volatile("ldmatrix.sync.aligned.m8n8.x4.shared.b16 {%0,%1,%2,%3}, [%4];"
        : "=r"(r[0]), "=r"(r[1]), "=r"(r[2]), "=r"(r[3]) : "r"(addr));
}
__device__ __forceinline__ void mma16816(float* c, const uint32_t* a,
                                         uint32_t b0, uint32_t b1) {
    asm volatile("mma.sync.aligned.m16n8k16.row.col.f32.bf16.bf16.f32 "
        "{%0,%1,%2,%3}, {%4,%5,%6,%7}, {%8,%9}, {%0,%1,%2,%3};"
        : "+f"(c[0]), "+f"(c[1]), "+f"(c[2]), "+f"(c[3])
        : "r"(a[0]), "r"(a[1]), "r"(a[2]), "r"(a[3]), "r"(b0), "r"(b1));
}

// Stage: 128 rows x 128B (8x16B chunks). Chunks 0-3 = A, 4-7 = B.
// XOR swizzle: slot = ch ^ (row & 7) -> conflict-free ldmatrix.
__device__ __forceinline__ uint32_t swadr(uint32_t base, int rowByte, int rm, int ch) {
    return base + rowByte + ((ch ^ rm) << 4);
}

#define STAGE_BYTES 16384
#define SCRATCH_OFF (2 * STAGE_BYTES)            // 32768: dedicated epilogue scratch
#define SMEM_TOTAL  (SCRATCH_OFF + 3072)         // 35840 B

// ---------------------------------------------------------------------------
// Kernel 1: L2-normalize rows -> g_hi (bf16). One warp per row.
// ---------------------------------------------------------------------------
__global__ void __launch_bounds__(256) normalize_kernel(const float* __restrict__ z1,
                                                        const float* __restrict__ z2) {
    const int row  = blockIdx.x * 8 + (threadIdx.x >> 5);
    const int lane = threadIdx.x & 31;
    const float* src = (row < N_ROWS) ? (z1 + (size_t)row * D)
                                      : (z2 + (size_t)(row - N_ROWS) * D);
    float4 a = reinterpret_cast<const float4*>(src)[lane];
    float4 b = reinterpret_cast<const float4*>(src)[lane + 32];
    float ss = a.x*a.x + a.y*a.y + a.z*a.z + a.w*a.w
             + b.x*b.x + b.y*b.y + b.z*b.z + b.w*b.w;
    #pragma unroll
    for (int off = 16; off > 0; off >>= 1)
        ss += __shfl_xor_sync(0xffffffffu, ss, off);
    float scale = 1.0f / fmaxf(sqrtf(ss), 1e-12f);

    float v[8] = {a.x*scale, a.y*scale, a.z*scale, a.w*scale,
                  b.x*scale, b.y*scale, b.z*scale, b.w*scale};
    __nv_bfloat162* dh = reinterpret_cast<__nv_bfloat162*>(g_hi + (size_t)row * D);
    dh[lane * 2 + 0]        = __halves2bfloat162(__float2bfloat16(v[0]), __float2bfloat16(v[1]));
    dh[lane * 2 + 1]        = __halves2bfloat162(__float2bfloat16(v[2]), __float2bfloat16(v[3]));
    dh[(lane + 32) * 2 + 0] = __halves2bfloat162(__float2bfloat16(v[4]), __float2bfloat16(v[5]));
    dh[(lane + 32) * 2 + 1] = __halves2bfloat162(__float2bfloat16(v[6]), __float2bfloat16(v[7]));
}

// ---------------------------------------------------------------------------
// Stage loader
// ---------------------------------------------------------------------------
__device__ __forceinline__ void load_stage(uint32_t stageAddr, int kt,
                                           int rowBase, int colBase, int tid) {
    const int kOff = kt * BK;
    #pragma unroll
    for (int i = 0; i < 4; i++) {
        const int v = i * 256 + tid;
        const int row = v >> 3, ch = v & 7;       // ch 0-3: A, 4-7: B
        const int gRow = (ch < 4) ? (rowBase + row) : (colBase + row);
        const void* src = g_hi + (size_t)gRow * D + kOff + (ch & 3) * 8;
        const uint32_t dst = stageAddr + row * 128 + ((ch ^ (row & 7)) << 4);
        CP_ASYNC16(dst, src);
    }
}

// Tile decode: b<1024 -> right half (bx=b>>5, ct=32+(b&31)); else triangular.
__device__ __forceinline__ void decode_tile(int b, int& bx, int& ct, bool& sym) {
    if (b < 1024) {
        bx = b >> 5; ct = 32 + (b & 31); sym = false;
    } else {
        const int t = b - 1024;
        int e = (int)((sqrtf(8.0f * t + 1.0f) - 1.0f) * 0.5f);
        while ((e + 1) * (e + 2) / 2 <= t) e++;
        while (e * (e + 1) / 2 > t) e--;
        bx = e; ct = t - e * (e + 1) / 2; sym = (ct != bx);
    }
}

// ---------------------------------------------------------------------------
// Kernel 2: persistent HMMA fused sim-GEMM + exp + row/col sums.
// 296 CTAs; tile b = blockIdx.x + k*296. Flat chunk pipeline continues across
// tile boundaries so next tile's first load overlaps this tile's epilogue.
// ---------------------------------------------------------------------------
__global__ void __launch_bounds__(256, 2) simsum_mma_kernel() {
    extern __shared__ char smem[];
    const uint32_t smem_u32 = smem_to_u32(smem);
    const int tid = threadIdx.x;

    const int lane  = tid & 31;
    const int w     = tid >> 5;
    const int warpM = w >> 1;
    const int warpN = w & 1;

    const int aRow  = warpM * 32 + (lane & 7) + ((lane >> 3) & 1) * 8;
    const int aCh   = (lane >> 4) & 1;
    const int aRm   = aRow & 7;
    const int bRow  = warpN * 64 + (lane & 7) + ((lane >> 4) & 1) * 8;
    const int bCh   = (lane >> 3) & 1;
    const int bRm   = bRow & 7;
    const int aRowByte[2] = {aRow * 128, (aRow + 16) * 128};
    const int bRowByte[4] = {bRow * 128, (bRow + 16) * 128,
                             (bRow + 32) * 128, (bRow + 48) * 128};

    float* rowScratch = reinterpret_cast<float*>(smem + SCRATCH_OFF);        // [2][128]
    float* colScratch = reinterpret_cast<float*>(smem + SCRATCH_OFF) + 256;  // [2][4][64]

    int tile = blockIdx.x;
    int bx, colTile; bool sym;
    decode_tile(tile, bx, colTile, sym);
    int rowBase = bx * BM, colBase = colTile * BN;

    int chunk = 0;                 // global chunk parity counter
    load_stage(smem_u32, 0, rowBase, colBase, tid);
    CP_COMMIT();

    #pragma unroll 1
    while (true) {
        // Decode next tile (for cross-tile prefetch)
        const int nxtTile = tile + GRID_GEMM;
        const bool hasNext = (nxtTile < NTILES);
        int nbx = 0, nct = 0; bool nsym = false;
        if (hasNext) decode_tile(nxtTile, nbx, nct, nsym);
        const int nRowBase = nbx * BM, nColBase = nct * BN;

        float acc[2][8][4];
        #pragma unroll
        for (int mt = 0; mt < 2; mt++)
            #pragma unroll
            for (int nt = 0; nt < 8; nt++)
                #pragma unroll
                for (int r = 0; r < 4; r++) acc[mt][nt][r] = 0.0f;

        #pragma unroll 1
        for (int kt = 0; kt < NKT; kt++) {
            const uint32_t stage = smem_u32 + (uint32_t)(chunk & 1) * STAGE_BYTES;
            const uint32_t nstage = smem_u32 + (uint32_t)((chunk + 1) & 1) * STAGE_BYTES;
            if (kt + 1 < NKT) {
                load_stage(nstage, kt + 1, rowBase, colBase, tid);
                CP_COMMIT(); CP_WAIT(1);
            } else if (hasNext) {
                load_stage(nstage, 0, nRowBase, nColBase, tid);
                CP_COMMIT(); CP_WAIT(1);
            } else {
                CP_WAIT(0);
            }
            __syncthreads();

            #pragma unroll
            for (int s = 0; s < 2; s++) {
                uint32_t ah[2][4], bh[4][4];
                #pragma unroll
                for (int mt = 0; mt < 2; mt++)
                    ldsm4(ah[mt], swadr(stage, aRowByte[mt], aRm, 2 * s + aCh));
                #pragma unroll
                for (int p = 0; p < 4; p++)
                    ldsm4(bh[p], swadr(stage, bRowByte[p], bRm, 4 + 2 * s + bCh));
                #pragma unroll
                for (int mt = 0; mt < 2; mt++)
                    #pragma unroll
                    for (int nt = 0; nt < 8; nt++)
                        mma16816(acc[mt][nt], ah[mt], bh[nt >> 1][(nt & 1) * 2],
                                 bh[nt >> 1][(nt & 1) * 2 + 1]);
            }
            __syncthreads();
            chunk++;
        }

        // ---------------- Epilogue (next tile's kt0 load is in flight) -------
        const float l2T = c_l2T;
        float rs0[2] = {0.0f, 0.0f}, rs1[2] = {0.0f, 0.0f};
        float cs[16];
        #pragma unroll
        for (int i = 0; i < 16; i++) cs[i] = 0.0f;

        #pragma unroll
        for (int mt = 0; mt < 2; mt++)
            #pragma unroll
            for (int nt = 0; nt < 8; nt++) {
                const float e0 = ex2(acc[mt][nt][0] * l2T);
                const float e1 = ex2(acc[mt][nt][1] * l2T);
                const float e2 = ex2(acc[mt][nt][2] * l2T);
                const float e3 = ex2(acc[mt][nt][3] * l2T);
                rs0[mt] += e0 + e1;
                rs1[mt] += e2 + e3;
                cs[nt * 2 + 0] += e0 + e2;
                cs[nt * 2 + 1] += e1 + e3;
            }

        #pragma unroll
        for (int off = 1; off <= 2; off <<= 1) {
            #pragma unroll
            for (int mt = 0; mt < 2; mt++) {
                rs0[mt] += __shfl_xor_sync(0xffffffffu, rs0[mt], off);
                rs1[mt] += __shfl_xor_sync(0xffffffffu, rs1[mt], off);
            }
        }
        if ((lane & 3) == 0) {
            const int r8 = lane >> 2;
            #pragma unroll
            for (int mt = 0; mt < 2; mt++) {
                rowScratch[warpN * 128 + warpM * 32 + mt * 16 + 0 + r8] = rs0[mt];
                rowScratch[warpN * 128 + warpM * 32 + mt * 16 + 8 + r8] = rs1[mt];
            }
        }
        if (sym) {
            #pragma unroll
            for (int i = 0; i < 16; i++) {
                #pragma unroll
                for (int off = 4; off <= 16; off <<= 1)
                    cs[i] += __shfl_xor_sync(0xffffffffu, cs[i], off);
            }
            if (lane < 4) {
                #pragma unroll
                for (int nt = 0; nt < 8; nt++) {
                    colScratch[(warpN * 4 + warpM) * 64 + nt * 8 + lane * 2 + 0] = cs[nt * 2 + 0];
                    colScratch[(warpN * 4 + warpM) * 64 + nt * 8 + lane * 2 + 1] = cs[nt * 2 + 1];
                }
            }
        }
        __syncthreads();

        if (tid < 128) {
            const float p = rowScratch[tid] + rowScratch[128 + tid];
            g_partial[(size_t)(rowBase + tid) * NCOLTILES + colTile] = p;
            if (sym) {
                const int wn = tid >> 6, ix = tid & 63;
                float c = colScratch[(wn * 4 + 0) * 64 + ix] + colScratch[(wn * 4 + 1) * 64 + ix]
                        + colScratch[(wn * 4 + 2) * 64 + ix] + colScratch[(wn * 4 + 3) * 64 + ix];
                g_partial[(size_t)(colBase + tid) * NCOLTILES + bx] = c;
            }
        }
        __syncthreads();   // scratch reuse safety for next tile

        if (!hasNext) break;
        tile = nxtTile; bx = nbx; colTile = nct; sym = nsym;
        rowBase = nRowBase; colBase = nColBase;
    }
}

// ---------------------------------------------------------------------------
// Kernel 3: per-row loss + grid-wide mean (last-block pattern, deterministic).
// Correction dots from the same bf16 plane the GEMM used (fp32 accumulation).
// ---------------------------------------------------------------------------
__global__ void __launch_bounds__(256) loss_reduce_kernel(float* __restrict__ out) {
    __shared__ float warpLoss[8];
    __shared__ int   isLast;
    const int bid  = blockIdx.x;
    const int row  = bid * 8 + (threadIdx.x >> 5);
    const int lane = threadIdx.x & 31;

    float total = g_partial[(size_t)row * NCOLTILES + lane]
                + g_partial[(size_t)row * NCOLTILES + lane + 32];

    // lane handles 8 consecutive bf16 (one uint4) of each 256-elem row
    const uint4 va = reinterpret_cast<const uint4*>(g_hi + (size_t)row * D)[lane];
    const uint4 vb = reinterpret_cast<const uint4*>(g_hi + (size_t)(N_ROWS + row) * D)[lane];
    const uint4 vc = reinterpret_cast<const uint4*>(g_hi + (size_t)N_ROWS * D)[lane];

    float dp = 0.0f, d0 = 0.0f;
    {
        const __nv_bfloat162* pa = reinterpret_cast<const __nv_bfloat162*>(&va);
        const __nv_bfloat162* pb = reinterpret_cast<const __nv_bfloat162*>(&vb);
        const __nv_bfloat162* pc = reinterpret_cast<const __nv_bfloat162*>(&vc);
        #pragma unroll
        for (int i = 0; i < 4; i++) {
            float2 fa = __bfloat1622float2(pa[i]);
            float2 fb = __bfloat1622float2(pb[i]);
            float2 fc = __bfloat1622float2(pc[i]);
            dp += fa.x * fb.x + fa.y * fb.y;
            d0 += fa.x * fc.x + fa.y * fc.y;
        }
    }
    #pragma unroll
    for (int off = 16; off > 0; off >>= 1) {
        total += __shfl_xor_sync(0xffffffffu, total, off);
        dp    += __shfl_xor_sync(0xffffffffu, dp, off);
        d0    += __shfl_xor_sync(0xffffffffu, d0, off);
    }
    if (lane == 0) {
        float sum_negs = total - ex2(d0 * c_l2T);
        warpLoss[threadIdx.x >> 5] = logf(sum_negs) - dp * c_invT;
    }
    __syncthreads();

    if (threadIdx.x == 0) {
        float bs = 0.0f;
        #pragma unroll
        for (int i = 0; i < 8; i++) bs += warpLoss[i];
        g_blocksum[bid] = bs;
        __threadfence();
        int old = atomicAdd(&g_counter, 1);
        isLast = (old == NLOSSBLK - 1);
    }
    __syncthreads();

    if (isLast) {
        __shared__ float s[256];
        float v = 0.0f;
        #pragma unroll
        for (int h = 0; h < 2; h++) {
            float t;
            asm volatile("ld.global.cg.f32 %0, [%1];" : "=f"(t)
                         : "l"(g_blocksum + threadIdx.x + h * 256));
            v += t;
        }
        s[threadIdx.x] = v;
        __syncthreads();
        #pragma unroll
        for (int stride = 128; stride > 0; stride >>= 1) {
            if (threadIdx.x < stride) s[threadIdx.x] += s[threadIdx.x + stride];
            __syncthreads();
        }
        if (threadIdx.x == 0) {
            out[0] = s[0] * (1.0f / N_ROWS);
            g_counter = 0;   // reset for graph replay
        }
    }
}

// ---------------------------------------------------------------------------
extern "C" void kernel_launch(void* const* d_in, const int* in_sizes, int n_in,
                              void* d_out, int out_size) {
    const float* z1 = (const float*)d_in[0];
    const float* z2 = (const float*)d_in[1];
    float* out = (float*)d_out;

    cudaFuncSetAttribute(simsum_mma_kernel,
                         cudaFuncAttributeMaxDynamicSharedMemorySize, SMEM_TOTAL);

    normalize_kernel<<<TWO_N / 8, 256>>>(z1, z2);
    simsum_mma_kernel<<<GRID_GEMM, 256, SMEM_TOTAL>>>();
    loss_reduce_kernel<<<NLOSSBLK, 256>>>(out);
}